// round 6
// baseline (speedup 1.0000x reference)
#include <cuda_runtime.h>

#define NN 50000
#define EE 800000
#define INDIM 768
#define HID 256
#define OUTD 128

// ---------------- scratch (static device globals; no allocation) -------------
__device__ int   g_is32;          // 1 -> edge_index is int32 layout, 0 -> int64
__device__ float g_deg[NN];
__device__ float g_dis[NN];
__device__ int   g_cnt[NN];
__device__ int   g_rp[NN + 1];
__device__ int   g_cur[NN];
__device__ int   g_col[EE];
__device__ float g_wn[EE];
__device__ float g_bufA[(size_t)NN * HID];   // 51.2 MB
__device__ float g_bufB[(size_t)NN * HID];   // 51.2 MB
__device__ float g_bufC[(size_t)NN * OUTD];  // 25.6 MB

// Fetch (src, dst) of edge e regardless of index dtype.
__device__ __forceinline__ int2 load_edge(const void* ei, int e) {
    if (g_is32) {
        const int* p = (const int*)ei;
        return make_int2(p[e], p[EE + e]);
    } else {
        const long long* p = (const long long*)ei;
        return make_int2((int)p[e], (int)p[EE + e]);
    }
}

// ---------------- graph preprocessing ----------------------------------------
__global__ void k_init() {
    int i = blockIdx.x * blockDim.x + threadIdx.x;
    if (i < NN) { g_deg[i] = 1.0f; g_cnt[i] = 0; }  // self-loop weight 1
    if (i == 0) g_is32 = 0;
}

// Probe index dtype: odd int32 words in the first EE elements are int64 high
// halves (always 0 for indices < 2^31) or int32 src values (random, ~never all 0).
// Reads stay within 2*EE int32 = the minimum possible buffer size.
__global__ void k_detect(const int* __restrict__ ei32) {
    int t = blockIdx.x * blockDim.x + threadIdx.x;
    if (t < EE) {
        if (ei32[2 * t + 1] != 0) g_is32 = 1;   // benign race: all writers store 1
    }
}

__global__ void k_degcnt(const void* __restrict__ ei, const float* __restrict__ ew) {
    int e = blockIdx.x * blockDim.x + threadIdx.x;
    if (e < EE) {
        int2 sd = load_edge(ei, e);
        atomicAdd(&g_deg[sd.y], ew[e]);
        atomicAdd(&g_cnt[sd.y], 1);
    }
}

__global__ void k_dis() {
    int i = blockIdx.x * blockDim.x + threadIdx.x;
    if (i < NN) g_dis[i] = rsqrtf(g_deg[i]);  // deg >= 1 always
}

// single-block exclusive scan over g_cnt -> g_rp (and g_cur copy)
__global__ void k_scan() {
    __shared__ int sdata[1024];
    int tid = threadIdx.x;
    const int n = NN;
    int chunk = (n + 1023) / 1024;
    int start = tid * chunk;
    int end = start + chunk; if (end > n) end = n;
    int s = 0;
    for (int i = start; i < end; i++) s += g_cnt[i];
    sdata[tid] = s;
    __syncthreads();
    for (int off = 1; off < 1024; off <<= 1) {
        int v = 0;
        if (tid >= off) v = sdata[tid - off];
        __syncthreads();
        if (tid >= off) sdata[tid] += v;
        __syncthreads();
    }
    int run = (tid > 0) ? sdata[tid - 1] : 0;
    for (int i = start; i < end; i++) {
        g_rp[i] = run;
        g_cur[i] = run;
        run += g_cnt[i];
    }
    if (tid == 1023) g_rp[n] = sdata[1023];
}

__global__ void k_fill(const void* __restrict__ ei, const float* __restrict__ ew) {
    int e = blockIdx.x * blockDim.x + threadIdx.x;
    if (e < EE) {
        int2 sd = load_edge(ei, e);
        int p = atomicAdd(&g_cur[sd.y], 1);
        g_col[p] = sd.x;
        g_wn[p] = g_dis[sd.x] * ew[e] * g_dis[sd.y];
    }
}

// ---------------- fp32 SGEMM: C[M,N] = A[M,K] @ B[K,N] (row-major) -----------
// Register-staged pipeline: next k-tile's global loads are issued before the
// current tile's compute, hiding L2 latency behind the FFMA block.
#define BM 128
#define BN 128
#define BK 8
#define TM 8
#define TN 8

__global__ __launch_bounds__(256) void sgemm(
    const float* __restrict__ A, const float* __restrict__ B, float* __restrict__ C,
    int M, int N, int K)
{
    __shared__ float As[BK][BM];
    __shared__ float Bs[BK][BN];
    int tid = threadIdx.x;
    int rowBase = blockIdx.y * BM;
    int colBase = blockIdx.x * BN;
    int tx = tid % 16, ty = tid / 16;

    int aRow = tid >> 1;           // 0..127
    int aCol = (tid & 1) * 4;      // 0 or 4
    int bRow = tid >> 5;           // 0..7
    int bCol = (tid & 31) * 4;     // 0..124

    int gRow = rowBase + aRow;
    bool aOk = (gRow < M);
    const float* aPtr = A + (size_t)(aOk ? gRow : 0) * K + aCol;
    const float* bPtr = B + (size_t)bRow * N + colBase + bCol;

    float acc[TM][TN];
#pragma unroll
    for (int i = 0; i < TM; i++)
#pragma unroll
        for (int j = 0; j < TN; j++) acc[i][j] = 0.0f;

    // prologue: load first k-tile into registers
    float4 av = make_float4(0.f, 0.f, 0.f, 0.f);
    if (aOk) av = *(const float4*)(aPtr);
    float4 bv = *(const float4*)(bPtr);

    for (int k0 = 0; k0 < K; k0 += BK) {
        // commit staged registers to shared
        As[aCol + 0][aRow] = av.x;
        As[aCol + 1][aRow] = av.y;
        As[aCol + 2][aRow] = av.z;
        As[aCol + 3][aRow] = av.w;
        *(float4*)&Bs[bRow][bCol] = bv;
        __syncthreads();

        // issue next tile's global loads (latency overlapped with compute below)
        int k1 = k0 + BK;
        if (k1 < K) {
            if (aOk) av = *(const float4*)(aPtr + k1);
            bv = *(const float4*)(bPtr + (size_t)k1 * N);
        }

#pragma unroll
        for (int k = 0; k < BK; k++) {
            float af[TM], bf[TN];
#pragma unroll
            for (int i = 0; i < TM; i++) af[i] = As[k][ty * TM + i];
#pragma unroll
            for (int j = 0; j < TN; j++) bf[j] = Bs[k][tx * TN + j];
#pragma unroll
            for (int i = 0; i < TM; i++)
#pragma unroll
                for (int j = 0; j < TN; j++) acc[i][j] += af[i] * bf[j];
        }
        __syncthreads();
    }

#pragma unroll
    for (int i = 0; i < TM; i++) {
        int r = rowBase + ty * TM + i;
        if (r < M) {
#pragma unroll
            for (int j = 0; j < TN; j += 4) {
                float4 v = make_float4(acc[i][j], acc[i][j + 1], acc[i][j + 2], acc[i][j + 3]);
                *(float4*)(C + (size_t)r * N + colBase + tx * TN + j) = v;
            }
        }
    }
}

// ---------------- gather-aggregate + bias + BN(eval) + ReLU (F = 256) --------
__global__ __launch_bounds__(256) void k_agg_bn_relu(
    const float* __restrict__ h, float* __restrict__ out,
    const float* __restrict__ b, const float* __restrict__ gamma,
    const float* __restrict__ beta, const float* __restrict__ mean,
    const float* __restrict__ var)
{
    int warp = (blockIdx.x * blockDim.x + threadIdx.x) >> 5;
    int lane = threadIdx.x & 31;
    if (warp >= NN) return;

    const float4* hb = (const float4*)h;
    float4 a0 = make_float4(0.f, 0.f, 0.f, 0.f);
    float4 a1 = a0;
    int s = g_rp[warp], e = g_rp[warp + 1];
    for (int i = s; i < e; i++) {
        int j = g_col[i];
        float w = g_wn[i];
        const float4* r = hb + (size_t)j * (HID / 4);
        float4 v0 = r[lane];
        float4 v1 = r[lane + 32];
        a0.x += w * v0.x; a0.y += w * v0.y; a0.z += w * v0.z; a0.w += w * v0.w;
        a1.x += w * v1.x; a1.y += w * v1.y; a1.z += w * v1.z; a1.w += w * v1.w;
    }
    {   // self-loop: norm = dis^2
        float w = g_dis[warp]; w *= w;
        const float4* r = hb + (size_t)warp * (HID / 4);
        float4 v0 = r[lane];
        float4 v1 = r[lane + 32];
        a0.x += w * v0.x; a0.y += w * v0.y; a0.z += w * v0.z; a0.w += w * v0.w;
        a1.x += w * v1.x; a1.y += w * v1.y; a1.z += w * v1.z; a1.w += w * v1.w;
    }

    float res[8] = {a0.x, a0.y, a0.z, a0.w, a1.x, a1.y, a1.z, a1.w};
    int fb[2] = {lane * 4, 128 + lane * 4};
#pragma unroll
    for (int half = 0; half < 2; half++) {
#pragma unroll
        for (int c = 0; c < 4; c++) {
            int f = fb[half] + c;
            float sc = gamma[f] * rsqrtf(var[f] + 1e-5f);
            float v = (res[half * 4 + c] + b[f] - mean[f]) * sc + beta[f];
            res[half * 4 + c] = fmaxf(v, 0.0f);
        }
    }
    float4* ob = (float4*)out + (size_t)warp * (HID / 4);
    ob[lane]      = make_float4(res[0], res[1], res[2], res[3]);
    ob[lane + 32] = make_float4(res[4], res[5], res[6], res[7]);
}

// ---------------- final gather-aggregate + bias + L2 normalize (F = 128) -----
__global__ __launch_bounds__(256) void k_agg_norm(
    const float* __restrict__ h, float* __restrict__ out, const float* __restrict__ b)
{
    int warp = (blockIdx.x * blockDim.x + threadIdx.x) >> 5;
    int lane = threadIdx.x & 31;
    if (warp >= NN) return;

    const float4* hb = (const float4*)h;
    float4 a = make_float4(0.f, 0.f, 0.f, 0.f);
    int s = g_rp[warp], e = g_rp[warp + 1];
    for (int i = s; i < e; i++) {
        int j = g_col[i];
        float w = g_wn[i];
        float4 v = hb[(size_t)j * (OUTD / 4) + lane];
        a.x += w * v.x; a.y += w * v.y; a.z += w * v.z; a.w += w * v.w;
    }
    {
        float w = g_dis[warp]; w *= w;
        float4 v = hb[(size_t)warp * (OUTD / 4) + lane];
        a.x += w * v.x; a.y += w * v.y; a.z += w * v.z; a.w += w * v.w;
    }
    float4 bb = ((const float4*)b)[lane];
    a.x += bb.x; a.y += bb.y; a.z += bb.z; a.w += bb.w;

    float ss = a.x * a.x + a.y * a.y + a.z * a.z + a.w * a.w;
#pragma unroll
    for (int off = 16; off > 0; off >>= 1)
        ss += __shfl_xor_sync(0xffffffffu, ss, off);
    float inv = 1.0f / fmaxf(sqrtf(ss), 1e-12f);
    a.x *= inv; a.y *= inv; a.z *= inv; a.w *= inv;
    ((float4*)out)[(size_t)warp * (OUTD / 4) + lane] = a;
}

// ---------------- launcher ----------------------------------------------------
extern "C" void kernel_launch(void* const* d_in, const int* in_sizes, int n_in,
                              void* d_out, int out_size)
{
    (void)in_sizes; (void)n_in; (void)out_size;
    const float* x   = (const float*)d_in[0];
    const void*  ei  = d_in[1];                 // int32 or int64 — probed at runtime
    const float* ew  = (const float*)d_in[2];
    const float* W1  = (const float*)d_in[3];
    const float* b1  = (const float*)d_in[4];
    const float* W2  = (const float*)d_in[5];
    const float* b2  = (const float*)d_in[6];
    const float* W3  = (const float*)d_in[7];
    const float* b3  = (const float*)d_in[8];
    const float* g1  = (const float*)d_in[9];
    const float* be1 = (const float*)d_in[10];
    const float* m1  = (const float*)d_in[11];
    const float* v1  = (const float*)d_in[12];
    const float* g2  = (const float*)d_in[13];
    const float* be2 = (const float*)d_in[14];
    const float* m2  = (const float*)d_in[15];
    const float* v2  = (const float*)d_in[16];

    float* bufA; cudaGetSymbolAddress((void**)&bufA, g_bufA);
    float* bufB; cudaGetSymbolAddress((void**)&bufB, g_bufB);
    float* bufC; cudaGetSymbolAddress((void**)&bufC, g_bufC);

    const int TB = 256;
    // graph preprocessing -> CSR keyed by dst
    k_init<<<(NN + TB - 1) / TB, TB>>>();
    k_detect<<<(EE + TB - 1) / TB, TB>>>((const int*)ei);
    k_degcnt<<<(EE + TB - 1) / TB, TB>>>(ei, ew);
    k_dis<<<(NN + TB - 1) / TB, TB>>>();
    k_scan<<<1, 1024>>>();
    k_fill<<<(EE + TB - 1) / TB, TB>>>(ei, ew);

    dim3 gemm_grid1(HID / BN, (NN + BM - 1) / BM);
    dim3 gemm_grid3(OUTD / BN, (NN + BM - 1) / BM);
    int agg_blocks = (NN * 32 + TB - 1) / TB;

    // layer 1
    sgemm<<<gemm_grid1, 256>>>(x, W1, bufA, NN, HID, INDIM);
    k_agg_bn_relu<<<agg_blocks, TB>>>(bufA, bufB, b1, g1, be1, m1, v1);
    // layer 2
    sgemm<<<gemm_grid1, 256>>>(bufB, W2, bufA, NN, HID, HID);
    k_agg_bn_relu<<<agg_blocks, TB>>>(bufA, bufB, b2, g2, be2, m2, v2);
    // layer 3
    sgemm<<<gemm_grid3, 256>>>(bufB, W3, bufC, NN, OUTD, HID);
    k_agg_norm<<<agg_blocks, TB>>>(bufC, (float*)d_out, b3);
}

// round 14
// speedup vs baseline: 1.3523x; 1.3523x over previous
#include <cuda_runtime.h>
#include <cuda_bf16.h>
#include <cstdint>

#define NN 50000
#define EE 800000
#define INDIM 768
#define HID 256
#define OUTD 128

// ---------------- scratch (static device globals; no allocation) -------------
__device__ int   g_is32;
__device__ float g_deg[NN];
__device__ float g_dis[NN];
__device__ int   g_cnt[NN];
__device__ int   g_rp[NN + 1];
__device__ int   g_cur[NN];
__device__ int   g_col[EE];
__device__ float g_wn[EE];
__device__ float g_bufA[(size_t)NN * HID];
__device__ float g_bufB[(size_t)NN * HID];
__device__ float g_bufC[(size_t)NN * OUTD];
// split-bf16 operands
__device__ __nv_bfloat16 g_xh[(size_t)NN * INDIM];
__device__ __nv_bfloat16 g_xl[(size_t)NN * INDIM];
__device__ __nv_bfloat16 g_hh[(size_t)NN * HID];
__device__ __nv_bfloat16 g_hl[(size_t)NN * HID];
__device__ __nv_bfloat16 g_w1h[HID * INDIM];
__device__ __nv_bfloat16 g_w1l[HID * INDIM];
__device__ __nv_bfloat16 g_w2h[HID * HID];
__device__ __nv_bfloat16 g_w2l[HID * HID];
__device__ __nv_bfloat16 g_w3h[OUTD * HID];
__device__ __nv_bfloat16 g_w3l[OUTD * HID];

// Fetch (src, dst) of edge e regardless of index dtype.
__device__ __forceinline__ int2 load_edge(const void* ei, int e) {
    if (g_is32) {
        const int* p = (const int*)ei;
        return make_int2(p[e], p[EE + e]);
    } else {
        const long long* p = (const long long*)ei;
        return make_int2((int)p[e], (int)p[EE + e]);
    }
}

// ---------------- graph preprocessing ----------------------------------------
__global__ void k_init() {
    int i = blockIdx.x * blockDim.x + threadIdx.x;
    if (i < NN) { g_deg[i] = 1.0f; g_cnt[i] = 0; }
    if (i == 0) g_is32 = 0;
}

__global__ void k_detect(const int* __restrict__ ei32) {
    int t = blockIdx.x * blockDim.x + threadIdx.x;
    if (t < EE) {
        if (ei32[2 * t + 1] != 0) g_is32 = 1;
    }
}

__global__ void k_degcnt(const void* __restrict__ ei, const float* __restrict__ ew) {
    int e = blockIdx.x * blockDim.x + threadIdx.x;
    if (e < EE) {
        int2 sd = load_edge(ei, e);
        atomicAdd(&g_deg[sd.y], ew[e]);
        atomicAdd(&g_cnt[sd.y], 1);
    }
}

__global__ void k_dis() {
    int i = blockIdx.x * blockDim.x + threadIdx.x;
    if (i < NN) g_dis[i] = rsqrtf(g_deg[i]);
}

__global__ void k_scan() {
    __shared__ int sdata[1024];
    int tid = threadIdx.x;
    const int n = NN;
    int chunk = (n + 1023) / 1024;
    int start = tid * chunk;
    int end = start + chunk; if (end > n) end = n;
    int s = 0;
    for (int i = start; i < end; i++) s += g_cnt[i];
    sdata[tid] = s;
    __syncthreads();
    for (int off = 1; off < 1024; off <<= 1) {
        int v = 0;
        if (tid >= off) v = sdata[tid - off];
        __syncthreads();
        if (tid >= off) sdata[tid] += v;
        __syncthreads();
    }
    int run = (tid > 0) ? sdata[tid - 1] : 0;
    for (int i = start; i < end; i++) {
        g_rp[i] = run;
        g_cur[i] = run;
        run += g_cnt[i];
    }
    if (tid == 1023) g_rp[n] = sdata[1023];
}

__global__ void k_fill(const void* __restrict__ ei, const float* __restrict__ ew) {
    int e = blockIdx.x * blockDim.x + threadIdx.x;
    if (e < EE) {
        int2 sd = load_edge(ei, e);
        int p = atomicAdd(&g_cur[sd.y], 1);
        g_col[p] = sd.x;
        g_wn[p] = g_dis[sd.x] * ew[e] * g_dis[sd.y];
    }
}

// ---------------- split fp32 -> bf16 hi/lo ------------------------------------
__global__ void k_split(const float* __restrict__ in, __nv_bfloat16* __restrict__ hi,
                        __nv_bfloat16* __restrict__ lo, int n) {
    int i = blockIdx.x * blockDim.x + threadIdx.x;
    if (i < n) {
        float v = in[i];
        __nv_bfloat16 h = __float2bfloat16(v);
        hi[i] = h;
        lo[i] = __float2bfloat16(v - __bfloat162float(h));
    }
}

// W [K,N] row-major -> hi/lo transposed [N,K] row-major
__global__ void k_wsplit(const float* __restrict__ W, __nv_bfloat16* __restrict__ hiT,
                         __nv_bfloat16* __restrict__ loT, int K, int N) {
    int idx = blockIdx.x * blockDim.x + threadIdx.x;
    if (idx < K * N) {
        int k = idx / N, n = idx % N;
        float v = W[idx];
        __nv_bfloat16 h = __float2bfloat16(v);
        hiT[(size_t)n * K + k] = h;
        loT[(size_t)n * K + k] = __float2bfloat16(v - __bfloat162float(h));
    }
}

// ---------------- mma.sync split-bf16 GEMM: C[M,N] = A[M,K] @ Bt[N,K]^T ------
// CTA 128x64, 8 warps (each 32x32), K staged 32/chunk in padded SMEM.
// Split-fp32: acc += Ah*Bh + Ah*Bl + Al*Bh  (3 HMMA per fragment pair).

__device__ __forceinline__ void mma16816(float* c, const uint32_t* a, const uint32_t* b) {
    asm volatile(
        "mma.sync.aligned.m16n8k16.row.col.f32.bf16.bf16.f32 "
        "{%0,%1,%2,%3}, {%4,%5,%6,%7}, {%8,%9}, {%0,%1,%2,%3};"
        : "+f"(c[0]), "+f"(c[1]), "+f"(c[2]), "+f"(c[3])
        : "r"(a[0]), "r"(a[1]), "r"(a[2]), "r"(a[3]), "r"(b[0]), "r"(b[1]));
}

#define KC 32            // K per SMEM stage
#define ROWSTRIDE 80     // bytes per SMEM row: 40 bf16 (32 data + 8 pad)

__global__ __launch_bounds__(256) void gemm_mma(
    const __nv_bfloat16* __restrict__ Ah, const __nv_bfloat16* __restrict__ Al,
    const __nv_bfloat16* __restrict__ Bh, const __nv_bfloat16* __restrict__ Bl,
    float* __restrict__ C, int M, int K, int N)
{
    __shared__ char sAh[128 * ROWSTRIDE];
    __shared__ char sAl[128 * ROWSTRIDE];
    __shared__ char sBh[64 * ROWSTRIDE];
    __shared__ char sBl[64 * ROWSTRIDE];

    int tid = threadIdx.x;
    int wid = tid >> 5, lane = tid & 31;
    int gid = lane >> 2, tig = lane & 3;
    int rowBase = blockIdx.y * 128;
    int nBase = blockIdx.x * 64;

    int mRowW = (wid & 3) * 32;     // warp M offset in CTA tile
    int nColW = (wid >> 2) * 32;    // warp N offset in CTA tile

    // loader indices: 256 threads; r = tid/4 (0..63), q = tid%4 (col chunk of 8)
    int lr = tid >> 2, lq = tid & 3;

    float acc[2][4][4];
#pragma unroll
    for (int i = 0; i < 2; i++)
#pragma unroll
        for (int j = 0; j < 4; j++)
#pragma unroll
            for (int t = 0; t < 4; t++) acc[i][j][t] = 0.0f;

    for (int k0 = 0; k0 < K; k0 += KC) {
        // ---- stage A (128 x 32) hi/lo ----
#pragma unroll
        for (int h = 0; h < 2; h++) {
            int row = h * 64 + lr;
            int grow = rowBase + row;
            uint4 vh = make_uint4(0, 0, 0, 0), vl = vh;
            if (grow < M) {
                vh = *(const uint4*)(Ah + (size_t)grow * K + k0 + lq * 8);
                vl = *(const uint4*)(Al + (size_t)grow * K + k0 + lq * 8);
            }
            *(uint4*)(sAh + row * ROWSTRIDE + lq * 16) = vh;
            *(uint4*)(sAl + row * ROWSTRIDE + lq * 16) = vl;
        }
        // ---- stage B (64 x 32) hi/lo ----
        {
            int row = lr;   // 0..63, all valid (N multiple of 64)
            uint4 vh = *(const uint4*)(Bh + (size_t)(nBase + row) * K + k0 + lq * 8);
            uint4 vl = *(const uint4*)(Bl + (size_t)(nBase + row) * K + k0 + lq * 8);
            *(uint4*)(sBh + row * ROWSTRIDE + lq * 16) = vh;
            *(uint4*)(sBl + row * ROWSTRIDE + lq * 16) = vl;
        }
        __syncthreads();

        // ---- compute: 2 k16 steps ----
#pragma unroll
        for (int ks = 0; ks < 2; ks++) {
            int kb = ks * 32;   // byte offset of k16 step (16 bf16 = 32 B)
            uint32_t ah[2][4], al[2][4], bh[4][2], bl[4][2];
#pragma unroll
            for (int i = 0; i < 2; i++) {
                int base = (mRowW + i * 16 + gid) * ROWSTRIDE + kb + tig * 4;
                ah[i][0] = *(const uint32_t*)(sAh + base);
                ah[i][1] = *(const uint32_t*)(sAh + base + 8 * ROWSTRIDE);
                ah[i][2] = *(const uint32_t*)(sAh + base + 16);
                ah[i][3] = *(const uint32_t*)(sAh + base + 8 * ROWSTRIDE + 16);
                al[i][0] = *(const uint32_t*)(sAl + base);
                al[i][1] = *(const uint32_t*)(sAl + base + 8 * ROWSTRIDE);
                al[i][2] = *(const uint32_t*)(sAl + base + 16);
                al[i][3] = *(const uint32_t*)(sAl + base + 8 * ROWSTRIDE + 16);
            }
#pragma unroll
            for (int j = 0; j < 4; j++) {
                int base = (nColW + j * 8 + gid) * ROWSTRIDE + kb + tig * 4;
                bh[j][0] = *(const uint32_t*)(sBh + base);
                bh[j][1] = *(const uint32_t*)(sBh + base + 16);
                bl[j][0] = *(const uint32_t*)(sBl + base);
                bl[j][1] = *(const uint32_t*)(sBl + base + 16);
            }
#pragma unroll
            for (int i = 0; i < 2; i++)
#pragma unroll
                for (int j = 0; j < 4; j++) {
                    mma16816(acc[i][j], ah[i], bh[j]);
                    mma16816(acc[i][j], ah[i], bl[j]);
                    mma16816(acc[i][j], al[i], bh[j]);
                }
        }
        __syncthreads();
    }

    // ---- epilogue ----
#pragma unroll
    for (int i = 0; i < 2; i++) {
#pragma unroll
        for (int j = 0; j < 4; j++) {
            int row0 = rowBase + mRowW + i * 16 + gid;
            int col = nBase + nColW + j * 8 + tig * 2;
            if (row0 < M)
                *(float2*)(C + (size_t)row0 * N + col) = make_float2(acc[i][j][0], acc[i][j][1]);
            int row1 = row0 + 8;
            if (row1 < M)
                *(float2*)(C + (size_t)row1 * N + col) = make_float2(acc[i][j][2], acc[i][j][3]);
        }
    }
}

// ---------------- gather-aggregate + bias + BN(eval) + ReLU (F = 256) --------
__global__ __launch_bounds__(256) void k_agg_bn_relu(
    const float* __restrict__ h, float* __restrict__ out,
    const float* __restrict__ b, const float* __restrict__ gamma,
    const float* __restrict__ beta, const float* __restrict__ mean,
    const float* __restrict__ var)
{
    int warp = (blockIdx.x * blockDim.x + threadIdx.x) >> 5;
    int lane = threadIdx.x & 31;
    if (warp >= NN) return;

    const float4* hb = (const float4*)h;
    float4 a0 = make_float4(0.f, 0.f, 0.f, 0.f);
    float4 a1 = a0;
    int s = g_rp[warp], e = g_rp[warp + 1];
    for (int i = s; i < e; i++) {
        int j = g_col[i];
        float w = g_wn[i];
        const float4* r = hb + (size_t)j * (HID / 4);
        float4 v0 = r[lane];
        float4 v1 = r[lane + 32];
        a0.x += w * v0.x; a0.y += w * v0.y; a0.z += w * v0.z; a0.w += w * v0.w;
        a1.x += w * v1.x; a1.y += w * v1.y; a1.z += w * v1.z; a1.w += w * v1.w;
    }
    {
        float w = g_dis[warp]; w *= w;
        const float4* r = hb + (size_t)warp * (HID / 4);
        float4 v0 = r[lane];
        float4 v1 = r[lane + 32];
        a0.x += w * v0.x; a0.y += w * v0.y; a0.z += w * v0.z; a0.w += w * v0.w;
        a1.x += w * v1.x; a1.y += w * v1.y; a1.z += w * v1.z; a1.w += w * v1.w;
    }

    float res[8] = {a0.x, a0.y, a0.z, a0.w, a1.x, a1.y, a1.z, a1.w};
    int fb[2] = {lane * 4, 128 + lane * 4};
#pragma unroll
    for (int half = 0; half < 2; half++) {
#pragma unroll
        for (int c = 0; c < 4; c++) {
            int f = fb[half] + c;
            float sc = gamma[f] * rsqrtf(var[f] + 1e-5f);
            float v = (res[half * 4 + c] + b[f] - mean[f]) * sc + beta[f];
            res[half * 4 + c] = fmaxf(v, 0.0f);
        }
    }
    float4* ob = (float4*)out + (size_t)warp * (HID / 4);
    ob[lane]      = make_float4(res[0], res[1], res[2], res[3]);
    ob[lane + 32] = make_float4(res[4], res[5], res[6], res[7]);
}

// ---------------- final gather-aggregate + bias + L2 normalize (F = 128) -----
__global__ __launch_bounds__(256) void k_agg_norm(
    const float* __restrict__ h, float* __restrict__ out, const float* __restrict__ b)
{
    int warp = (blockIdx.x * blockDim.x + threadIdx.x) >> 5;
    int lane = threadIdx.x & 31;
    if (warp >= NN) return;

    const float4* hb = (const float4*)h;
    float4 a = make_float4(0.f, 0.f, 0.f, 0.f);
    int s = g_rp[warp], e = g_rp[warp + 1];
    for (int i = s; i < e; i++) {
        int j = g_col[i];
        float w = g_wn[i];
        float4 v = hb[(size_t)j * (OUTD / 4) + lane];
        a.x += w * v.x; a.y += w * v.y; a.z += w * v.z; a.w += w * v.w;
    }
    {
        float w = g_dis[warp]; w *= w;
        float4 v = hb[(size_t)warp * (OUTD / 4) + lane];
        a.x += w * v.x; a.y += w * v.y; a.z += w * v.z; a.w += w * v.w;
    }
    float4 bb = ((const float4*)b)[lane];
    a.x += bb.x; a.y += bb.y; a.z += bb.z; a.w += bb.w;

    float ss = a.x * a.x + a.y * a.y + a.z * a.z + a.w * a.w;
#pragma unroll
    for (int off = 16; off > 0; off >>= 1)
        ss += __shfl_xor_sync(0xffffffffu, ss, off);
    float inv = 1.0f / fmaxf(sqrtf(ss), 1e-12f);
    a.x *= inv; a.y *= inv; a.z *= inv; a.w *= inv;
    ((float4*)out)[(size_t)warp * (OUTD / 4) + lane] = a;
}

// ---------------- launcher ----------------------------------------------------
extern "C" void kernel_launch(void* const* d_in, const int* in_sizes, int n_in,
                              void* d_out, int out_size)
{
    (void)in_sizes; (void)n_in; (void)out_size;
    const float* x   = (const float*)d_in[0];
    const void*  ei  = d_in[1];
    const float* ew  = (const float*)d_in[2];
    const float* W1  = (const float*)d_in[3];
    const float* b1  = (const float*)d_in[4];
    const float* W2  = (const float*)d_in[5];
    const float* b2  = (const float*)d_in[6];
    const float* W3  = (const float*)d_in[7];
    const float* b3  = (const float*)d_in[8];
    const float* g1  = (const float*)d_in[9];
    const float* be1 = (const float*)d_in[10];
    const float* m1  = (const float*)d_in[11];
    const float* v1  = (const float*)d_in[12];
    const float* g2  = (const float*)d_in[13];
    const float* be2 = (const float*)d_in[14];
    const float* m2  = (const float*)d_in[15];
    const float* v2  = (const float*)d_in[16];

    float *bufA, *bufB, *bufC;
    __nv_bfloat16 *xh, *xl, *hh, *hl, *w1h, *w1l, *w2h, *w2l, *w3h, *w3l;
    cudaGetSymbolAddress((void**)&bufA, g_bufA);
    cudaGetSymbolAddress((void**)&bufB, g_bufB);
    cudaGetSymbolAddress((void**)&bufC, g_bufC);
    cudaGetSymbolAddress((void**)&xh, g_xh);
    cudaGetSymbolAddress((void**)&xl, g_xl);
    cudaGetSymbolAddress((void**)&hh, g_hh);
    cudaGetSymbolAddress((void**)&hl, g_hl);
    cudaGetSymbolAddress((void**)&w1h, g_w1h);
    cudaGetSymbolAddress((void**)&w1l, g_w1l);
    cudaGetSymbolAddress((void**)&w2h, g_w2h);
    cudaGetSymbolAddress((void**)&w2l, g_w2l);
    cudaGetSymbolAddress((void**)&w3h, g_w3h);
    cudaGetSymbolAddress((void**)&w3l, g_w3l);

    const int TB = 256;
    // graph preprocessing -> CSR keyed by dst
    k_init<<<(NN + TB - 1) / TB, TB>>>();
    k_detect<<<(EE + TB - 1) / TB, TB>>>((const int*)ei);
    k_degcnt<<<(EE + TB - 1) / TB, TB>>>(ei, ew);
    k_dis<<<(NN + TB - 1) / TB, TB>>>();
    k_scan<<<1, 1024>>>();
    k_fill<<<(EE + TB - 1) / TB, TB>>>(ei, ew);

    // weight splits (transposed to [N,K])
    k_wsplit<<<(INDIM * HID + TB - 1) / TB, TB>>>(W1, w1h, w1l, INDIM, HID);
    k_wsplit<<<(HID * HID + TB - 1) / TB, TB>>>(W2, w2h, w2l, HID, HID);
    k_wsplit<<<(HID * OUTD + TB - 1) / TB, TB>>>(W3, w3h, w3l, HID, OUTD);

    int Mtiles = (NN + 127) / 128;
    int agg_blocks = (NN * 32 + TB - 1) / TB;

    // layer 1
    k_split<<<(NN * INDIM + TB - 1) / TB, TB>>>(x, xh, xl, NN * INDIM);
    gemm_mma<<<dim3(HID / 64, Mtiles), 256>>>(xh, xl, w1h, w1l, bufA, NN, INDIM, HID);
    k_agg_bn_relu<<<agg_blocks, TB>>>(bufA, bufB, b1, g1, be1, m1, v1);
    // layer 2
    k_split<<<(NN * HID + TB - 1) / TB, TB>>>(bufB, hh, hl, NN * HID);
    gemm_mma<<<dim3(HID / 64, Mtiles), 256>>>(hh, hl, w2h, w2l, bufA, NN, HID, HID);
    k_agg_bn_relu<<<agg_blocks, TB>>>(bufA, bufB, b2, g2, be2, m2, v2);
    // layer 3
    k_split<<<(NN * HID + TB - 1) / TB, TB>>>(bufB, hh, hl, NN * HID);
    gemm_mma<<<dim3(OUTD / 64, Mtiles), 256>>>(hh, hl, w3h, w3l, bufC, NN, HID, OUTD);
    k_agg_norm<<<agg_blocks, TB>>>(bufC, (float*)d_out, b3);
}

// round 17
// speedup vs baseline: 1.3996x; 1.0350x over previous
#include <cuda_runtime.h>
#include <cuda_bf16.h>
#include <cstdint>

#define NN 50000
#define EE 800000
#define INDIM 768
#define HID 256
#define OUTD 128

// ---------------- scratch (static device globals; no allocation) -------------
__device__ int   g_is32;
__device__ float g_deg[NN];
__device__ float g_dis[NN];
__device__ int   g_cnt[NN];
__device__ int   g_rp[NN + 1];
__device__ int   g_cur[NN];
__device__ float g_bufA[(size_t)NN * HID];
__device__ float g_bufC[(size_t)NN * OUTD];
__device__ int   g_col[EE];
__device__ float g_wn[EE];
// split-bf16 operands
__device__ __nv_bfloat16 g_xh[(size_t)NN * INDIM];
__device__ __nv_bfloat16 g_xl[(size_t)NN * INDIM];
__device__ __nv_bfloat16 g_hh[(size_t)NN * HID];
__device__ __nv_bfloat16 g_hl[(size_t)NN * HID];
__device__ __nv_bfloat16 g_w1h[HID * INDIM];
__device__ __nv_bfloat16 g_w1l[HID * INDIM];
__device__ __nv_bfloat16 g_w2h[HID * HID];
__device__ __nv_bfloat16 g_w2l[HID * HID];
__device__ __nv_bfloat16 g_w3h[OUTD * HID];
__device__ __nv_bfloat16 g_w3l[OUTD * HID];

// Fetch (src, dst) of edge e regardless of index dtype.
__device__ __forceinline__ int2 load_edge(const void* ei, int e) {
    if (g_is32) {
        const int* p = (const int*)ei;
        return make_int2(p[e], p[EE + e]);
    } else {
        const long long* p = (const long long*)ei;
        return make_int2((int)p[e], (int)p[EE + e]);
    }
}

// ---------------- graph preprocessing ----------------------------------------
__global__ void k_init() {
    int i = blockIdx.x * blockDim.x + threadIdx.x;
    if (i < NN) { g_deg[i] = 1.0f; g_cnt[i] = 0; }
    if (i == 0) g_is32 = 0;
}

__global__ void k_detect(const int* __restrict__ ei32) {
    int t = blockIdx.x * blockDim.x + threadIdx.x;
    if (t < EE) {
        if (ei32[2 * t + 1] != 0) g_is32 = 1;
    }
}

__global__ void k_degcnt(const void* __restrict__ ei, const float* __restrict__ ew) {
    int e = blockIdx.x * blockDim.x + threadIdx.x;
    if (e < EE) {
        int2 sd = load_edge(ei, e);
        atomicAdd(&g_deg[sd.y], ew[e]);
        atomicAdd(&g_cnt[sd.y], 1);
    }
}

__global__ void k_dis() {
    int i = blockIdx.x * blockDim.x + threadIdx.x;
    if (i < NN) g_dis[i] = rsqrtf(g_deg[i]);
}

__global__ void k_scan() {
    __shared__ int sdata[1024];
    int tid = threadIdx.x;
    const int n = NN;
    int chunk = (n + 1023) / 1024;
    int start = tid * chunk;
    int end = start + chunk; if (end > n) end = n;
    int s = 0;
    for (int i = start; i < end; i++) s += g_cnt[i];
    sdata[tid] = s;
    __syncthreads();
    for (int off = 1; off < 1024; off <<= 1) {
        int v = 0;
        if (tid >= off) v = sdata[tid - off];
        __syncthreads();
        if (tid >= off) sdata[tid] += v;
        __syncthreads();
    }
    int run = (tid > 0) ? sdata[tid - 1] : 0;
    for (int i = start; i < end; i++) {
        g_rp[i] = run;
        g_cur[i] = run;
        run += g_cnt[i];
    }
    if (tid == 1023) g_rp[n] = sdata[1023];
}

__global__ void k_fill(const void* __restrict__ ei, const float* __restrict__ ew) {
    int e = blockIdx.x * blockDim.x + threadIdx.x;
    if (e < EE) {
        int2 sd = load_edge(ei, e);
        int p = atomicAdd(&g_cur[sd.y], 1);
        g_col[p] = sd.x;
        g_wn[p] = g_dis[sd.x] * ew[e] * g_dis[sd.y];
    }
}

// ---------------- split fp32 -> bf16 hi/lo (layer-1 input only) ---------------
__global__ void k_split(const float* __restrict__ in, __nv_bfloat16* __restrict__ hi,
                        __nv_bfloat16* __restrict__ lo, int n) {
    int i = blockIdx.x * blockDim.x + threadIdx.x;
    if (i < n) {
        float v = in[i];
        __nv_bfloat16 h = __float2bfloat16(v);
        hi[i] = h;
        lo[i] = __float2bfloat16(v - __bfloat162float(h));
    }
}

// W [K,N] row-major -> hi/lo transposed [N,K] row-major
__global__ void k_wsplit(const float* __restrict__ W, __nv_bfloat16* __restrict__ hiT,
                         __nv_bfloat16* __restrict__ loT, int K, int N) {
    int idx = blockIdx.x * blockDim.x + threadIdx.x;
    if (idx < K * N) {
        int k = idx / N, n = idx % N;
        float v = W[idx];
        __nv_bfloat16 h = __float2bfloat16(v);
        hiT[(size_t)n * K + k] = h;
        loT[(size_t)n * K + k] = __float2bfloat16(v - __bfloat162float(h));
    }
}

// ---------------- mma.sync split-bf16 GEMM: C[M,N] = A[M,K] @ Bt[N,K]^T ------
// CTA 128x64, 8 warps (each 32x32), K staged 32/chunk in padded SMEM.
// Register-prefetch pipeline: next chunk's global loads issued before compute.
// Split-fp32: acc += Ah*Bh + Ah*Bl + Al*Bh  (3 HMMA per fragment pair).

__device__ __forceinline__ void mma16816(float* c, const uint32_t* a, const uint32_t* b) {
    asm volatile(
        "mma.sync.aligned.m16n8k16.row.col.f32.bf16.bf16.f32 "
        "{%0,%1,%2,%3}, {%4,%5,%6,%7}, {%8,%9}, {%0,%1,%2,%3};"
        : "+f"(c[0]), "+f"(c[1]), "+f"(c[2]), "+f"(c[3])
        : "r"(a[0]), "r"(a[1]), "r"(a[2]), "r"(a[3]), "r"(b[0]), "r"(b[1]));
}

#define KC 32            // K per SMEM stage
#define ROWSTRIDE 80     // bytes per SMEM row: 40 bf16 (32 data + 8 pad)

__global__ __launch_bounds__(256) void gemm_mma(
    const __nv_bfloat16* __restrict__ Ah, const __nv_bfloat16* __restrict__ Al,
    const __nv_bfloat16* __restrict__ Bh, const __nv_bfloat16* __restrict__ Bl,
    float* __restrict__ C, int M, int K, int N)
{
    __shared__ char sAh[128 * ROWSTRIDE];
    __shared__ char sAl[128 * ROWSTRIDE];
    __shared__ char sBh[64 * ROWSTRIDE];
    __shared__ char sBl[64 * ROWSTRIDE];

    int tid = threadIdx.x;
    int wid = tid >> 5, lane = tid & 31;
    int gid = lane >> 2, tig = lane & 3;
    int rowBase = blockIdx.y * 128;
    int nBase = blockIdx.x * 64;

    int mRowW = (wid & 3) * 32;     // warp M offset in CTA tile
    int nColW = (wid >> 2) * 32;    // warp N offset in CTA tile

    // loader indices: 256 threads; r = tid/4 (0..63), q = tid%4 (col chunk of 8)
    int lr = tid >> 2, lq = tid & 3;

    // per-thread load coordinates (fixed per chunk)
    int rowA0 = lr,        growA0 = rowBase + rowA0;
    int rowA1 = 64 + lr,   growA1 = rowBase + rowA1;
    bool okA0 = growA0 < M, okA1 = growA1 < M;
    const __nv_bfloat16* pAh0 = Ah + (size_t)(okA0 ? growA0 : 0) * K + lq * 8;
    const __nv_bfloat16* pAl0 = Al + (size_t)(okA0 ? growA0 : 0) * K + lq * 8;
    const __nv_bfloat16* pAh1 = Ah + (size_t)(okA1 ? growA1 : 0) * K + lq * 8;
    const __nv_bfloat16* pAl1 = Al + (size_t)(okA1 ? growA1 : 0) * K + lq * 8;
    const __nv_bfloat16* pBh = Bh + (size_t)(nBase + lr) * K + lq * 8;
    const __nv_bfloat16* pBl = Bl + (size_t)(nBase + lr) * K + lq * 8;

    float acc[2][4][4];
#pragma unroll
    for (int i = 0; i < 2; i++)
#pragma unroll
        for (int j = 0; j < 4; j++)
#pragma unroll
            for (int t = 0; t < 4; t++) acc[i][j][t] = 0.0f;

    uint4 z = make_uint4(0, 0, 0, 0);
    // prologue: load chunk 0 into registers
    uint4 rAh0 = okA0 ? *(const uint4*)(pAh0) : z;
    uint4 rAl0 = okA0 ? *(const uint4*)(pAl0) : z;
    uint4 rAh1 = okA1 ? *(const uint4*)(pAh1) : z;
    uint4 rAl1 = okA1 ? *(const uint4*)(pAl1) : z;
    uint4 rBh  = *(const uint4*)(pBh);
    uint4 rBl  = *(const uint4*)(pBl);

    for (int k0 = 0; k0 < K; k0 += KC) {
        // commit staged registers to SMEM
        *(uint4*)(sAh + rowA0 * ROWSTRIDE + lq * 16) = rAh0;
        *(uint4*)(sAl + rowA0 * ROWSTRIDE + lq * 16) = rAl0;
        *(uint4*)(sAh + rowA1 * ROWSTRIDE + lq * 16) = rAh1;
        *(uint4*)(sAl + rowA1 * ROWSTRIDE + lq * 16) = rAl1;
        *(uint4*)(sBh + lr * ROWSTRIDE + lq * 16) = rBh;
        *(uint4*)(sBl + lr * ROWSTRIDE + lq * 16) = rBl;
        __syncthreads();

        // prefetch next chunk (latency hidden behind HMMA block below)
        int k1 = k0 + KC;
        if (k1 < K) {
            rAh0 = okA0 ? *(const uint4*)(pAh0 + k1) : z;
            rAl0 = okA0 ? *(const uint4*)(pAl0 + k1) : z;
            rAh1 = okA1 ? *(const uint4*)(pAh1 + k1) : z;
            rAl1 = okA1 ? *(const uint4*)(pAl1 + k1) : z;
            rBh  = *(const uint4*)(pBh + k1);
            rBl  = *(const uint4*)(pBl + k1);
        }

        // ---- compute: 2 k16 steps ----
#pragma unroll
        for (int ks = 0; ks < 2; ks++) {
            int kb = ks * 32;   // byte offset of k16 step (16 bf16 = 32 B)
            uint32_t ah[2][4], al[2][4], bh[4][2], bl[4][2];
#pragma unroll
            for (int i = 0; i < 2; i++) {
                int base = (mRowW + i * 16 + gid) * ROWSTRIDE + kb + tig * 4;
                ah[i][0] = *(const uint32_t*)(sAh + base);
                ah[i][1] = *(const uint32_t*)(sAh + base + 8 * ROWSTRIDE);
                ah[i][2] = *(const uint32_t*)(sAh + base + 16);
                ah[i][3] = *(const uint32_t*)(sAh + base + 8 * ROWSTRIDE + 16);
                al[i][0] = *(const uint32_t*)(sAl + base);
                al[i][1] = *(const uint32_t*)(sAl + base + 8 * ROWSTRIDE);
                al[i][2] = *(const uint32_t*)(sAl + base + 16);
                al[i][3] = *(const uint32_t*)(sAl + base + 8 * ROWSTRIDE + 16);
            }
#pragma unroll
            for (int j = 0; j < 4; j++) {
                int base = (nColW + j * 8 + gid) * ROWSTRIDE + kb + tig * 4;
                bh[j][0] = *(const uint32_t*)(sBh + base);
                bh[j][1] = *(const uint32_t*)(sBh + base + 16);
                bl[j][0] = *(const uint32_t*)(sBl + base);
                bl[j][1] = *(const uint32_t*)(sBl + base + 16);
            }
#pragma unroll
            for (int i = 0; i < 2; i++)
#pragma unroll
                for (int j = 0; j < 4; j++) {
                    mma16816(acc[i][j], ah[i], bh[j]);
                    mma16816(acc[i][j], ah[i], bl[j]);
                    mma16816(acc[i][j], al[i], bh[j]);
                }
        }
        __syncthreads();
    }

    // ---- epilogue ----
#pragma unroll
    for (int i = 0; i < 2; i++) {
#pragma unroll
        for (int j = 0; j < 4; j++) {
            int row0 = rowBase + mRowW + i * 16 + gid;
            int col = nBase + nColW + j * 8 + tig * 2;
            if (row0 < M)
                *(float2*)(C + (size_t)row0 * N + col) = make_float2(acc[i][j][0], acc[i][j][1]);
            int row1 = row0 + 8;
            if (row1 < M)
                *(float2*)(C + (size_t)row1 * N + col) = make_float2(acc[i][j][2], acc[i][j][3]);
        }
    }
}

// ------ gather-aggregate + bias + BN(eval) + ReLU + hi/lo split (F = 256) ----
// Emits bf16 hi/lo directly (sole consumer is the next GEMM) — kills k_split.
__global__ __launch_bounds__(256) void k_agg_bn_relu_split(
    const float* __restrict__ h,
    __nv_bfloat16* __restrict__ oh, __nv_bfloat16* __restrict__ ol,
    const float* __restrict__ b, const float* __restrict__ gamma,
    const float* __restrict__ beta, const float* __restrict__ mean,
    const float* __restrict__ var)
{
    int warp = (blockIdx.x * blockDim.x + threadIdx.x) >> 5;
    int lane = threadIdx.x & 31;
    if (warp >= NN) return;

    const float4* hb = (const float4*)h;
    float4 a0 = make_float4(0.f, 0.f, 0.f, 0.f);
    float4 a1 = a0;
    int s = g_rp[warp], e = g_rp[warp + 1];
    for (int i = s; i < e; i++) {
        int j = g_col[i];
        float w = g_wn[i];
        const float4* r = hb + (size_t)j * (HID / 4);
        float4 v0 = r[lane];
        float4 v1 = r[lane + 32];
        a0.x += w * v0.x; a0.y += w * v0.y; a0.z += w * v0.z; a0.w += w * v0.w;
        a1.x += w * v1.x; a1.y += w * v1.y; a1.z += w * v1.z; a1.w += w * v1.w;
    }
    {
        float w = g_dis[warp]; w *= w;
        const float4* r = hb + (size_t)warp * (HID / 4);
        float4 v0 = r[lane];
        float4 v1 = r[lane + 32];
        a0.x += w * v0.x; a0.y += w * v0.y; a0.z += w * v0.z; a0.w += w * v0.w;
        a1.x += w * v1.x; a1.y += w * v1.y; a1.z += w * v1.z; a1.w += w * v1.w;
    }

    float res[8] = {a0.x, a0.y, a0.z, a0.w, a1.x, a1.y, a1.z, a1.w};
    int fb[2] = {lane * 4, 128 + lane * 4};
#pragma unroll
    for (int half = 0; half < 2; half++) {
        union { __nv_bfloat16 v[4]; uint2 u; } ph, pl;
#pragma unroll
        for (int c = 0; c < 4; c++) {
            int f = fb[half] + c;
            float sc = gamma[f] * rsqrtf(var[f] + 1e-5f);
            float v = (res[half * 4 + c] + b[f] - mean[f]) * sc + beta[f];
            v = fmaxf(v, 0.0f);
            __nv_bfloat16 hv = __float2bfloat16(v);
            ph.v[c] = hv;
            pl.v[c] = __float2bfloat16(v - __bfloat162float(hv));
        }
        *(uint2*)(oh + (size_t)warp * HID + fb[half]) = ph.u;
        *(uint2*)(ol + (size_t)warp * HID + fb[half]) = pl.u;
    }
}

// ---------------- final gather-aggregate + bias + L2 normalize (F = 128) -----
__global__ __launch_bounds__(256) void k_agg_norm(
    const float* __restrict__ h, float* __restrict__ out, const float* __restrict__ b)
{
    int warp = (blockIdx.x * blockDim.x + threadIdx.x) >> 5;
    int lane = threadIdx.x & 31;
    if (warp >= NN) return;

    const float4* hb = (const float4*)h;
    float4 a = make_float4(0.f, 0.f, 0.f, 0.f);
    int s = g_rp[warp], e = g_rp[warp + 1];
    for (int i = s; i < e; i++) {
        int j = g_col[i];
        float w = g_wn[i];
        float4 v = hb[(size_t)j * (OUTD / 4) + lane];
        a.x += w * v.x; a.y += w * v.y; a.z += w * v.z; a.w += w * v.w;
    }
    {
        float w = g_dis[warp]; w *= w;
        float4 v = hb[(size_t)warp * (OUTD / 4) + lane];
        a.x += w * v.x; a.y += w * v.y; a.z += w * v.z; a.w += w * v.w;
    }
    float4 bb = ((const float4*)b)[lane];
    a.x += bb.x; a.y += bb.y; a.z += bb.z; a.w += bb.w;

    float ss = a.x * a.x + a.y * a.y + a.z * a.z + a.w * a.w;
#pragma unroll
    for (int off = 16; off > 0; off >>= 1)
        ss += __shfl_xor_sync(0xffffffffu, ss, off);
    float inv = 1.0f / fmaxf(sqrtf(ss), 1e-12f);
    a.x *= inv; a.y *= inv; a.z *= inv; a.w *= inv;
    ((float4*)out)[(size_t)warp * (OUTD / 4) + lane] = a;
}

// ---------------- launcher ----------------------------------------------------
extern "C" void kernel_launch(void* const* d_in, const int* in_sizes, int n_in,
                              void* d_out, int out_size)
{
    (void)in_sizes; (void)n_in; (void)out_size;
    const float* x   = (const float*)d_in[0];
    const void*  ei  = d_in[1];
    const float* ew  = (const float*)d_in[2];
    const float* W1  = (const float*)d_in[3];
    const float* b1  = (const float*)d_in[4];
    const float* W2  = (const float*)d_in[5];
    const float* b2  = (const float*)d_in[6];
    const float* W3  = (const float*)d_in[7];
    const float* b3  = (const float*)d_in[8];
    const float* g1  = (const float*)d_in[9];
    const float* be1 = (const float*)d_in[10];
    const float* m1  = (const float*)d_in[11];
    const float* v1  = (const float*)d_in[12];
    const float* g2  = (const float*)d_in[13];
    const float* be2 = (const float*)d_in[14];
    const float* m2  = (const float*)d_in[15];
    const float* v2  = (const float*)d_in[16];

    float *bufA, *bufC;
    __nv_bfloat16 *xh, *xl, *hh, *hl, *w1h, *w1l, *w2h, *w2l, *w3h, *w3l;
    cudaGetSymbolAddress((void**)&bufA, g_bufA);
    cudaGetSymbolAddress((void**)&bufC, g_bufC);
    cudaGetSymbolAddress((void**)&xh, g_xh);
    cudaGetSymbolAddress((void**)&xl, g_xl);
    cudaGetSymbolAddress((void**)&hh, g_hh);
    cudaGetSymbolAddress((void**)&hl, g_hl);
    cudaGetSymbolAddress((void**)&w1h, g_w1h);
    cudaGetSymbolAddress((void**)&w1l, g_w1l);
    cudaGetSymbolAddress((void**)&w2h, g_w2h);
    cudaGetSymbolAddress((void**)&w2l, g_w2l);
    cudaGetSymbolAddress((void**)&w3h, g_w3h);
    cudaGetSymbolAddress((void**)&w3l, g_w3l);

    const int TB = 256;
    // graph preprocessing -> CSR keyed by dst
    k_init<<<(NN + TB - 1) / TB, TB>>>();
    k_detect<<<(EE + TB - 1) / TB, TB>>>((const int*)ei);
    k_degcnt<<<(EE + TB - 1) / TB, TB>>>(ei, ew);
    k_dis<<<(NN + TB - 1) / TB, TB>>>();
    k_scan<<<1, 1024>>>();
    k_fill<<<(EE + TB - 1) / TB, TB>>>(ei, ew);

    // weight splits (transposed to [N,K])
    k_wsplit<<<(INDIM * HID + TB - 1) / TB, TB>>>(W1, w1h, w1l, INDIM, HID);
    k_wsplit<<<(HID * HID + TB - 1) / TB, TB>>>(W2, w2h, w2l, HID, HID);
    k_wsplit<<<(HID * OUTD + TB - 1) / TB, TB>>>(W3, w3h, w3l, HID, OUTD);

    int Mtiles = (NN + 127) / 128;
    int agg_blocks = (NN * 32 + TB - 1) / TB;

    // layer 1
    k_split<<<(NN * INDIM + TB - 1) / TB, TB>>>(x, xh, xl, NN * INDIM);
    gemm_mma<<<dim3(HID / 64, Mtiles), 256>>>(xh, xl, w1h, w1l, bufA, NN, INDIM, HID);
    k_agg_bn_relu_split<<<agg_blocks, TB>>>(bufA, hh, hl, b1, g1, be1, m1, v1);
    // layer 2
    gemm_mma<<<dim3(HID / 64, Mtiles), 256>>>(hh, hl, w2h, w2l, bufA, NN, HID, HID);
    k_agg_bn_relu_split<<<agg_blocks, TB>>>(bufA, hh, hl, b2, g2, be2, m2, v2);
    // layer 3
    gemm_mma<<<dim3(OUTD / 64, Mtiles), 256>>>(hh, hl, w3h, w3l, bufC, NN, HID, OUTD);
    k_agg_norm<<<agg_blocks, TB>>>(bufC, (float*)d_out, b3);
}